// round 7
// baseline (speedup 1.0000x reference)
#include <cuda_runtime.h>
#include <math.h>

// Problem shape (fixed by the benchmark):
// video [B=8, C=1024, T=64, W=14, H=14] fp32
// params mu_x, mu_y, sigma_x, sigma_y: [N=3] fp32
// out [B, C*N] = einsum('bctwh,nwh->bcn', video, filters) / T
#define N_FILT 3
#define W_DIM 14
#define H_DIM 14
#define WH 196              // W*H
#define WH4 49              // WH/4
#define T_DIM 64
#define T_GROUPS 5          // time-slices per CTA thread-group
#define ACTIVE_THREADS (WH4 * T_GROUPS)  // 245
#define SLAB (T_DIM * WH)   // 12544 floats per (b,c)
#define SLAB4 (SLAB / 4)    // 3136 float4 per (b,c)

// Filters pre-scaled by 1/(sum+eps) * (1/T), stored as float4 for vector LDG.
__device__ float4 g_filt4[N_FILT * WH4];

// ---------------------------------------------------------------------------
// Pre-kernel: 3 blocks, one per filter. 224 threads (196 active). Paid once.
// ---------------------------------------------------------------------------
__global__ void filter_kernel(const float* __restrict__ mu_x,
                              const float* __restrict__ mu_y,
                              const float* __restrict__ sigma_x,
                              const float* __restrict__ sigma_y) {
    const int n = blockIdx.x;
    const int tid = threadIdx.x;
    __shared__ float red[7];

    float mx = tanhf(mu_x[n]);
    float my = tanhf(mu_y[n]);
    float sgx = 1.0f / (1.0f + expf(-sigma_x[n]));
    float sgy = 1.0f / (1.0f + expf(-sigma_y[n]));
    float sx = expf(1.5f - 2.0f * sgx);
    float sy = expf(1.5f - 2.0f * sgy);
    float inv_x = 1.0f / (sx * sx + 1e-6f);
    float inv_y = 1.0f / (sy * sy + 1e-6f);
    float mux = (float)(W_DIM - 1) * ((mx + 1.0f) * 0.5f);
    float muy = (float)(H_DIM - 1) * ((my + 1.0f) * 0.5f);

    float v = 0.0f;
    if (tid < WH) {
        int w = tid / H_DIM;
        int h = tid - w * H_DIM;
        float dx = (float)w - mux;
        float dy = (float)h - muy;
        v = expf(-0.5f * (dx * dx * inv_x + dy * dy * inv_y));
    }
    float s = v;
    #pragma unroll
    for (int off = 16; off > 0; off >>= 1)
        s += __shfl_xor_sync(0xFFFFFFFFu, s, off);
    if ((tid & 31) == 0) red[tid >> 5] = s;
    __syncthreads();
    float tot = 0.0f;
    #pragma unroll
    for (int w = 0; w < 7; w++) tot += red[w];
    float scale = 1.0f / ((tot + 1e-6f) * (float)T_DIM);
    if (tid < WH) {
        ((float*)g_filt4)[n * WH + tid] = v * scale;
    }
}

// ---------------------------------------------------------------------------
// Main kernel: one CTA per PAIR of (b,c) slabs, processed SEQUENTIALLY with
// shared filter registers and a single combined epilogue. Each thread owns
// one spatial float4 position p; inner loop = 1 LDG.128 + 12 FFMA.
// 7 CTAs/SM (56 warps, above the ~40-warp HBM saturation knee) gives
// 4096/(148*7)=3.95 waves with a 95%-full last wave and 3 wave transitions.
// ---------------------------------------------------------------------------
__global__ __launch_bounds__(256, 7)
void pool_kernel(const float4* __restrict__ video4, float* __restrict__ out,
                 int n_bc, int n_half) {
    const int tid = threadIdx.x;
    const int bc0 = blockIdx.x;
    const int bc1 = blockIdx.x + n_half;
    const bool has1 = (bc1 < n_bc);

    float a0 = 0.0f, a1 = 0.0f, a2 = 0.0f;   // slab 0
    float b0 = 0.0f, b1 = 0.0f, b2 = 0.0f;   // slab 1

    if (tid < ACTIVE_THREADS) {
        const int g = tid / WH4;        // time-group 0..4
        const int p = tid - g * WH4;    // spatial float4 position 0..48

        const float4 f0 = g_filt4[p];
        const float4 f1 = g_filt4[WH4 + p];
        const float4 f2 = g_filt4[2 * WH4 + p];

        const int iters = (g == T_GROUPS - 1) ? 12 : 13;  // ceil((64-g)/5)

        const float4* vp = video4 + bc0 * SLAB4 + g * WH4 + p;
        #pragma unroll 2
        for (int it = 0; it < iters; it++) {
            float4 v = __ldg(vp);
            vp += T_GROUPS * WH4;
            a0 += v.x * f0.x + v.y * f0.y + v.z * f0.z + v.w * f0.w;
            a1 += v.x * f1.x + v.y * f1.y + v.z * f1.z + v.w * f1.w;
            a2 += v.x * f2.x + v.y * f2.y + v.z * f2.z + v.w * f2.w;
        }

        if (has1) {
            const float4* wp = video4 + bc1 * SLAB4 + g * WH4 + p;
            #pragma unroll 2
            for (int it = 0; it < iters; it++) {
                float4 v = __ldg(wp);
                wp += T_GROUPS * WH4;
                b0 += v.x * f0.x + v.y * f0.y + v.z * f0.z + v.w * f0.w;
                b1 += v.x * f1.x + v.y * f1.y + v.z * f1.z + v.w * f1.w;
                b2 += v.x * f2.x + v.y * f2.y + v.z * f2.z + v.w * f2.w;
            }
        }
    }

    // combined warp reduction of all 6 accumulators
    #pragma unroll
    for (int off = 16; off > 0; off >>= 1) {
        a0 += __shfl_xor_sync(0xFFFFFFFFu, a0, off);
        a1 += __shfl_xor_sync(0xFFFFFFFFu, a1, off);
        a2 += __shfl_xor_sync(0xFFFFFFFFu, a2, off);
        b0 += __shfl_xor_sync(0xFFFFFFFFu, b0, off);
        b1 += __shfl_xor_sync(0xFFFFFFFFu, b1, off);
        b2 += __shfl_xor_sync(0xFFFFFFFFu, b2, off);
    }

    __shared__ float part[8][2 * N_FILT];
    const int wid = tid >> 5;
    const int lid = tid & 31;
    if (lid == 0) {
        part[wid][0] = a0;
        part[wid][1] = a1;
        part[wid][2] = a2;
        part[wid][3] = b0;
        part[wid][4] = b1;
        part[wid][5] = b2;
    }
    __syncthreads();

    if (tid < 2 * N_FILT) {
        float s = 0.0f;
        #pragma unroll
        for (int w = 0; w < 8; w++) s += part[w][tid];
        if (tid < N_FILT) {
            out[bc0 * N_FILT + tid] = s;
        } else if (has1) {
            out[bc1 * N_FILT + (tid - N_FILT)] = s;
        }
    }
}

// ---------------------------------------------------------------------------
extern "C" void kernel_launch(void* const* d_in, const int* in_sizes, int n_in,
                              void* d_out, int out_size) {
    const float* video   = (const float*)d_in[0];
    const float* mu_x    = (const float*)d_in[1];
    const float* mu_y    = (const float*)d_in[2];
    const float* sigma_x = (const float*)d_in[3];
    const float* sigma_y = (const float*)d_in[4];
    float* out = (float*)d_out;

    const int n_bc = in_sizes[0] / SLAB;   // B*C = 8192
    const int n_half = (n_bc + 1) / 2;     // 4096

    filter_kernel<<<N_FILT, 224>>>(mu_x, mu_y, sigma_x, sigma_y);
    pool_kernel<<<n_half, 256>>>((const float4*)video, out, n_bc, n_half);
}

// round 8
// speedup vs baseline: 1.1584x; 1.1584x over previous
#include <cuda_runtime.h>
#include <math.h>

// Problem shape (fixed by the benchmark):
// video [B=8, C=1024, T=64, W=14, H=14] fp32
// params mu_x, mu_y, sigma_x, sigma_y: [N=3] fp32
// out [B, C*N] = einsum('bctwh,nwh->bcn', video, filters) / T
#define N_FILT 3
#define W_DIM 14
#define H_DIM 14
#define WH 196              // W*H
#define WH4 49              // WH/4
#define T_DIM 64
#define T_GROUPS 5          // time-slices per CTA thread-group
#define ACTIVE_THREADS (WH4 * T_GROUPS)  // 245
#define SLAB (T_DIM * WH)   // 12544 floats per (b,c)
#define SLAB4 (SLAB / 4)    // 3136 float4 per (b,c)

// Filters pre-scaled by 1/(sum+eps) * (1/T), stored as float4 for vector LDG.
__device__ float4 g_filt4[N_FILT * WH4];

// ---------------------------------------------------------------------------
// Pre-kernel: 3 blocks, one per filter. 224 threads (196 active). Paid once.
// ---------------------------------------------------------------------------
__global__ void filter_kernel(const float* __restrict__ mu_x,
                              const float* __restrict__ mu_y,
                              const float* __restrict__ sigma_x,
                              const float* __restrict__ sigma_y) {
    const int n = blockIdx.x;
    const int tid = threadIdx.x;
    __shared__ float red[7];

    float mx = tanhf(mu_x[n]);
    float my = tanhf(mu_y[n]);
    float sgx = 1.0f / (1.0f + expf(-sigma_x[n]));
    float sgy = 1.0f / (1.0f + expf(-sigma_y[n]));
    float sx = expf(1.5f - 2.0f * sgx);
    float sy = expf(1.5f - 2.0f * sgy);
    float inv_x = 1.0f / (sx * sx + 1e-6f);
    float inv_y = 1.0f / (sy * sy + 1e-6f);
    float mux = (float)(W_DIM - 1) * ((mx + 1.0f) * 0.5f);
    float muy = (float)(H_DIM - 1) * ((my + 1.0f) * 0.5f);

    float v = 0.0f;
    if (tid < WH) {
        int w = tid / H_DIM;
        int h = tid - w * H_DIM;
        float dx = (float)w - mux;
        float dy = (float)h - muy;
        v = expf(-0.5f * (dx * dx * inv_x + dy * dy * inv_y));
    }
    float s = v;
    #pragma unroll
    for (int off = 16; off > 0; off >>= 1)
        s += __shfl_xor_sync(0xFFFFFFFFu, s, off);
    if ((tid & 31) == 0) red[tid >> 5] = s;
    __syncthreads();
    float tot = 0.0f;
    #pragma unroll
    for (int w = 0; w < 7; w++) tot += red[w];
    float scale = 1.0f / ((tot + 1e-6f) * (float)T_DIM);
    if (tid < WH) {
        ((float*)g_filt4)[n * WH + tid] = v * scale;
    }
}

// ---------------------------------------------------------------------------
// Main kernel (identical hot loop to the 66.1us best): one CTA per (b,c)
// slab, thread owns one spatial float4 position p with 3 filter float4s in
// registers, strides time t = g, g+5, ... Inner loop: 1 LDG.128 + 12 FFMA.
// 8 CTAs/SM (32 regs): 8192/(148*8)=6.92 waves, 92%-full tail.
// Launched with PDL: grid-dependency sync before reading g_filt4 so the
// launch/setup overlaps the filter kernel instead of serializing behind it.
// ---------------------------------------------------------------------------
__global__ __launch_bounds__(256, 8)
void pool_kernel(const float4* __restrict__ video4, float* __restrict__ out) {
    const int bc = blockIdx.x;
    const int tid = threadIdx.x;

#if __CUDA_ARCH__ >= 900
    cudaGridDependencySynchronize();
#endif

    float a0 = 0.0f, a1 = 0.0f, a2 = 0.0f;

    if (tid < ACTIVE_THREADS) {
        const int g = tid / WH4;        // time-group 0..4
        const int p = tid - g * WH4;    // spatial float4 position 0..48

        const float4 f0 = g_filt4[p];
        const float4 f1 = g_filt4[WH4 + p];
        const float4 f2 = g_filt4[2 * WH4 + p];

        const float4* vp = video4 + bc * SLAB4 + g * WH4 + p;
        const int iters = (g == T_GROUPS - 1) ? 12 : 13;  // ceil((64-g)/5)

        #pragma unroll 2
        for (int it = 0; it < iters; it++) {
            float4 v = __ldg(vp);
            vp += T_GROUPS * WH4;
            a0 += v.x * f0.x + v.y * f0.y + v.z * f0.z + v.w * f0.w;
            a1 += v.x * f1.x + v.y * f1.y + v.z * f1.z + v.w * f1.w;
            a2 += v.x * f2.x + v.y * f2.y + v.z * f2.z + v.w * f2.w;
        }
    }

    // warp reduction (all 256 threads participate; inactive ones carry zeros)
    #pragma unroll
    for (int off = 16; off > 0; off >>= 1) {
        a0 += __shfl_xor_sync(0xFFFFFFFFu, a0, off);
        a1 += __shfl_xor_sync(0xFFFFFFFFu, a1, off);
        a2 += __shfl_xor_sync(0xFFFFFFFFu, a2, off);
    }

    __shared__ float part[8][N_FILT];
    const int wid = tid >> 5;
    const int lid = tid & 31;
    if (lid == 0) {
        part[wid][0] = a0;
        part[wid][1] = a1;
        part[wid][2] = a2;
    }
    __syncthreads();

    if (tid < N_FILT) {
        float s = 0.0f;
        #pragma unroll
        for (int w = 0; w < 8; w++) s += part[w][tid];
        out[bc * N_FILT + tid] = s;
    }
}

// ---------------------------------------------------------------------------
extern "C" void kernel_launch(void* const* d_in, const int* in_sizes, int n_in,
                              void* d_out, int out_size) {
    const float* video   = (const float*)d_in[0];
    const float* mu_x    = (const float*)d_in[1];
    const float* mu_y    = (const float*)d_in[2];
    const float* sigma_x = (const float*)d_in[3];
    const float* sigma_y = (const float*)d_in[4];
    float* out = (float*)d_out;

    const int n_bc = in_sizes[0] / SLAB;  // B*C = 8192

    filter_kernel<<<N_FILT, 224>>>(mu_x, mu_y, sigma_x, sigma_y);

    // Pool launched with programmatic dependent launch: it may begin while
    // filter_kernel is still running; cudaGridDependencySynchronize() inside
    // pool_kernel guarantees g_filt4 visibility before it is read.
    cudaLaunchConfig_t cfg = {};
    cfg.gridDim = dim3((unsigned)n_bc, 1, 1);
    cfg.blockDim = dim3(256, 1, 1);
    cfg.dynamicSmemBytes = 0;
    cfg.stream = 0;
    cudaLaunchAttribute attrs[1];
    attrs[0].id = cudaLaunchAttributeProgrammaticStreamSerialization;
    attrs[0].val.programmaticStreamSerializationAllowed = 1;
    cfg.attrs = attrs;
    cfg.numAttrs = 1;
    cudaLaunchKernelEx(&cfg, pool_kernel, (const float4*)video, out);
}